// round 14
// baseline (speedup 1.0000x reference)
#include <cuda_runtime.h>

#define NN 1024
#define BN 4096
#define NH 8
#define TI 8
#define TJ 16

typedef unsigned long long ull;

// ---- scratch ----
__device__ float g_V[BN*128];
__device__ float g_SKIP[BN*128];
__device__ float g_A1[BN*NH];
__device__ float g_A2[BN*NH];     // pre-scaled by CAF
__device__ float g_ATTG[4*NH];

#define CAF 0.7285541162061872f   // 0.505 * log2(e)
#define CBOCA 0.9801980198019802f // 0.495 / 0.505

// ---- packed f32x2 helpers ----
__device__ __forceinline__ ull ffma2(ull a, ull b, ull c) {
    ull d; asm("fma.rn.f32x2 %0,%1,%2,%3;" : "=l"(d) : "l"(a), "l"(b), "l"(c)); return d;
}
__device__ __forceinline__ ull fadd2(ull a, ull b) {
    ull d; asm("add.rn.f32x2 %0,%1,%2;" : "=l"(d) : "l"(a), "l"(b)); return d;
}
__device__ __forceinline__ ull fsub2(ull a, ull b) {
    ull d; asm("sub.rn.f32x2 %0,%1,%2;" : "=l"(d) : "l"(a), "l"(b)); return d;
}
__device__ __forceinline__ ull fmul2(ull a, ull b) {
    ull d; asm("mul.rn.f32x2 %0,%1,%2;" : "=l"(d) : "l"(a), "l"(b)); return d;
}
__device__ __forceinline__ ull pack2(float x, float y) {
    ull r; asm("mov.b64 %0,{%1,%2};" : "=l"(r) : "f"(x), "f"(y)); return r;
}
__device__ __forceinline__ float2 unpack2(ull v) {
    float2 r; asm("mov.b64 {%0,%1},%2;" : "=f"(r.x), "=f"(r.y) : "l"(v)); return r;
}
__device__ __forceinline__ ull shflx2(ull v, int m) {
    unsigned lo = (unsigned)v, hi = (unsigned)(v >> 32);
    lo = __shfl_xor_sync(0xffffffffu, lo, m);
    hi = __shfl_xor_sync(0xffffffffu, hi, m);
    return ((ull)hi << 32) | (ull)lo;
}

// ---- cp.async ----
__device__ __forceinline__ void cpa16(unsigned dst, const void* src) {
    asm volatile("cp.async.cg.shared.global [%0], [%1], 16;" :: "r"(dst), "l"(src));
}
__device__ __forceinline__ void cp_commit() {
    asm volatile("cp.async.commit_group;" ::: "memory");
}
__device__ __forceinline__ void cp_wait0() {
    asm volatile("cp.async.wait_group 0;" ::: "memory");
}

// ---- attn smem layout (float words) ----
// edge: 2 x 2592  ([i]*324 + j*20 + d)
// vals: 2 x 2592  ([h]*324 + j*20 + d)
// t:    1312      ([h]*164 + i*20 + j)
// adj:  2 x 160   ([i]*20 + j, ints)
// a2:   2 x 128   ([j]*8 + h)
#define EDGE_OFF(buf) ((buf) ? 2592 : 0)
#define VALS_OFF(buf) ((buf) ? 7776 : 5184)
#define T_OFF         10368
#define ADJ_OFF(buf)  ((buf) ? 11840 : 11680)
#define A2_OFF(buf)   ((buf) ? 12128 : 12000)
#define SMEM_WORDS    12256                    // 49024 bytes

// =====================================================================
// Kernel A: per-node GEMMs (R13's proven version; g_A2 pre-scaled).
// =====================================================================
#define ZSTR 260
#define PW_OFF 4160
#define PREP_WORDS (4160 + 8192)
#define NSTAGE 16
__global__ __launch_bounds__(256, 3) void gat_prep(
    const float* __restrict__ node, const float* __restrict__ hidden,
    const float* __restrict__ m_w,  const float* __restrict__ m_b,
    const float* __restrict__ skip_w, const float* __restrict__ skip_b,
    const float* __restrict__ a1_w, const float* __restrict__ a1_b,
    const float* __restrict__ a2_w, const float* __restrict__ a2_b,
    const float* __restrict__ graph, const float* __restrict__ ag_w,
    const float* __restrict__ ag_b)
{
    extern __shared__ float sm[];
    float* zs = sm;
    const unsigned sb = (unsigned)__cvta_generic_to_shared(sm);

    const int tid = threadIdx.x;
    const int r0  = blockIdx.x * 16;

    for (int t = tid; t < 16*64; t += 256) {
        int r = t >> 6, q = t & 63;
        float4 v = (q < 32) ? ((const float4*)node)[(r0 + r)*32 + q]
                            : ((const float4*)hidden)[(r0 + r)*32 + (q - 32)];
        *(float4*)&zs[r*ZSTR + q*4] = v;
    }

    const float* wsrc[4];
    unsigned     wdst[4];
    #pragma unroll
    for (int k4 = 0; k4 < 4; ++k4) {
        int c = tid + 256*k4;
        int m = c >> 9, cc = c & 511;
        int kl = cc >> 5, q4 = cc & 31;
        wsrc[k4] = (m ? skip_w : m_w) + kl*128 + q4*4;
        wdst[k4] = (unsigned)(m*2048 + kl*128 + q4*4)*4u;
    }

    {
        unsigned base = sb + (unsigned)PW_OFF*4u;
        #pragma unroll
        for (int k4 = 0; k4 < 4; ++k4) cpa16(base + wdst[k4], wsrc[k4]);
        #pragma unroll
        for (int k4 = 0; k4 < 4; ++k4) wsrc[k4] += 16*128;
    }
    cp_commit();

    const int cg = tid & 31;
    const int rg = tid >> 5;
    const int c0 = cg * 4;
    const int rowb = rg * 2;

    ull av[2][2], ak[2][2];
    {
        ulonglong2 bv = *(const ulonglong2*)&m_b[c0];
        ulonglong2 bk = *(const ulonglong2*)&skip_b[c0];
        #pragma unroll
        for (int rr = 0; rr < 2; ++rr) {
            av[rr][0] = bv.x; av[rr][1] = bv.y;
            ak[rr][0] = bk.x; ak[rr][1] = bk.y;
        }
    }
    const float* z0p = &zs[rowb*ZSTR];
    const float* z1p = &zs[(rowb + 1)*ZSTR];

    for (int s = 0; s < NSTAGE; ++s) {
        const int buf = s & 1;
        cp_wait0();
        __syncthreads();

        if (s + 1 < NSTAGE) {
            unsigned base = sb + (unsigned)(PW_OFF + (buf ^ 1)*4096)*4u;
            #pragma unroll
            for (int k4 = 0; k4 < 4; ++k4) cpa16(base + wdst[k4], wsrc[k4]);
            #pragma unroll
            for (int k4 = 0; k4 < 4; ++k4) wsrc[k4] += 16*128;
        }
        cp_commit();

        const float* wv = &sm[PW_OFF + buf*4096 + c0];
        const float* wk = wv + 2048;
        const int k0 = s*16;
        #pragma unroll
        for (int kl = 0; kl < 16; ++kl) {
            ulonglong2 WV = *(const ulonglong2*)(wv + kl*128);
            ulonglong2 WK = *(const ulonglong2*)(wk + kl*128);
            float z0 = z0p[k0 + kl], z1 = z1p[k0 + kl];
            ull zz0 = pack2(z0, z0), zz1 = pack2(z1, z1);
            av[0][0] = ffma2(zz0, WV.x, av[0][0]);
            av[0][1] = ffma2(zz0, WV.y, av[0][1]);
            av[1][0] = ffma2(zz1, WV.x, av[1][0]);
            av[1][1] = ffma2(zz1, WV.y, av[1][1]);
            ak[0][0] = ffma2(zz0, WK.x, ak[0][0]);
            ak[0][1] = ffma2(zz0, WK.y, ak[0][1]);
            ak[1][0] = ffma2(zz1, WK.x, ak[1][0]);
            ak[1][1] = ffma2(zz1, WK.y, ak[1][1]);
        }
    }
    #pragma unroll
    for (int rr = 0; rr < 2; ++rr) {
        int rowg = r0 + rowb + rr;
        ulonglong2 o;
        o.x = av[rr][0]; o.y = av[rr][1];
        *(ulonglong2*)&g_V[rowg*128 + c0] = o;
        o.x = ak[rr][0]; o.y = ak[rr][1];
        *(ulonglong2*)&g_SKIP[rowg*128 + c0] = o;
    }

    float* ws = sm + PW_OFF;
    __syncthreads();
    for (int t = tid; t < 2048; t += 256) {
        ws[t] = a1_w[t];
        ws[2048 + t] = a2_w[t];
    }
    __syncthreads();
    if (tid < 128) {
        int row = tid >> 3, h = tid & 7;
        float a1a = a1_b[h], a1c = 0.0f, a2a = a2_b[h], a2c = 0.0f;
        const float* zp = &zs[row*ZSTR];
        #pragma unroll 8
        for (int k = 0; k < 128; ++k) {
            float za = zp[k], zb = zp[k + 128];
            a1a = fmaf(za, ws[k*8 + h], a1a);
            a1c = fmaf(zb, ws[(k + 128)*8 + h], a1c);
            a2a = fmaf(za, ws[2048 + k*8 + h], a2a);
            a2c = fmaf(zb, ws[2048 + (k + 128)*8 + h], a2c);
        }
        g_A1[(r0 + row)*8 + h] = a1a + a1c;
        g_A2[(r0 + row)*8 + h] = (a2a + a2c) * CAF;
    } else if (blockIdx.x == 0 && tid < 160) {
        int t = tid - 128;
        int b = t >> 3, h = t & 7;
        float acc = ag_b[h];
        #pragma unroll 8
        for (int k = 0; k < 128; ++k)
            acc = fmaf(graph[b*128 + k], ag_w[k*8 + h], acc);
        g_ATTG[t] = acc;
    }
}

// =====================================================================
// Kernel C: fused attention. TI=8, TJ=16, grid 512, 3 CTAs/SM.
// Phase A: warp w = row i, lane (jl, hp): 2 head-pair tasks.
// Phase B: thread = (h=warp, i=lane>>2, jq): 4 j's, one i.
// =====================================================================
__global__ __launch_bounds__(256, 3) void gat_attn(
    const float* __restrict__ edge, const int* __restrict__ adj,
    const float* __restrict__ ae_w, const float* __restrict__ ae_b,
    float* __restrict__ out)
{
    extern __shared__ float smf[];
    const unsigned sb = (unsigned)__cvta_generic_to_shared(smf);

    const int tid = threadIdx.x;
    const int b   = blockIdx.x >> 7;     // 128 blocks per batch
    const int it  = blockIdx.x & 127;
    const int i0  = it * TI;
    const int bi  = b*NN + i0;

    const int w  = tid >> 5;              // phase A: i; phase B: h
    const int hp = tid & 3;
    const int jl = (tid >> 2) & 7;
    const int iB = (tid >> 2) & 7;         // phase B i (lane>>2)
    const int jq = tid & 3;                // phase B j-quarter

    // head-pair ae_w (d-pair packed), pre-scaled by CAF
    ull wh0[8], wh1[8];
    #pragma unroll
    for (int q = 0; q < 8; ++q) {
        wh0[q] = pack2(ae_w[(2*q)*8 + 2*hp]*CAF,     ae_w[(2*q+1)*8 + 2*hp]*CAF);
        wh1[q] = pack2(ae_w[(2*q)*8 + 2*hp + 1]*CAF, ae_w[(2*q+1)*8 + 2*hp + 1]*CAF);
    }
    ull baseA;
    {
        float g0 = g_ATTG[b*8 + 2*hp]     + ae_b[2*hp];
        float g1 = g_ATTG[b*8 + 2*hp + 1] + ae_b[2*hp + 1];
        const float* a1p = &g_A1[(size_t)(bi + w)*8 + 2*hp];
        baseA = pack2((a1p[0] + g0)*CAF, (a1p[1] + g1)*CAF);
    }

    const ull CBO2   = pack2(CBOCA, CBOCA);
    const ull NEG60  = pack2(-60.0f, -60.0f);
    const ull MAGIC2 = pack2(12582912.0f, 12582912.0f);
    const ull P4     = pack2(0.0096181291f, 0.0096181291f);
    const ull P3     = pack2(0.0555041087f, 0.0555041087f);
    const ull P2     = pack2(0.2402265070f, 0.2402265070f);
    const ull P1     = pack2(0.6931471806f, 0.6931471806f);
    const ull ONE2   = pack2(1.0f, 1.0f);

    ull acc[8];
    #pragma unroll
    for (int q = 0; q < 8; ++q) acc[q] = 0ull;
    ull s2 = 0ull;

    // ---- cp.async pointers ----
    // edge/vals: chunk id = tid (+256): r = tid>>6, j = (tid&63)>>2, d4 = tid&3
    const int cr = tid >> 6, cj = (tid & 63) >> 2, cd = tid & 3;
    const float* e_src = edge + ((size_t)(bi + cr)*NN + cj)*16 + cd*4;
    const unsigned e_dst = (unsigned)(cr*324 + cj*20 + cd*4)*4u;
    const float* v_src = g_V + (size_t)(b*NN + cj)*128 + cr*16 + cd*4;
    const unsigned v_dst = e_dst;   // same layout
    // adj (tid<32): i = tid>>2, q = tid&3
    const int*   adj_src = adj + (size_t)(bi + (tid >> 2))*NN + (tid & 3)*4;
    const unsigned adj_dst = (unsigned)((tid >> 2)*20 + (tid & 3)*4)*4u;
    // a2 (tid in [32,64)): c = tid-32: j = c>>1, hf = c&1
    const float* a2_src = g_A2 + (size_t)(b*NN + ((tid - 32) >> 1))*8 + (tid & 1)*4;
    const unsigned a2_dst = (unsigned)(((tid - 32) >> 1)*8 + (tid & 1)*4)*4u;

    #define ISSUE_TILE(BUF)                                                   \
    {                                                                         \
        unsigned eb = sb + (unsigned)EDGE_OFF(BUF)*4u;                        \
        unsigned vb = sb + (unsigned)VALS_OFF(BUF)*4u;                        \
        cpa16(eb + e_dst, e_src);                                             \
        cpa16(eb + e_dst + 1296u*4u, e_src + (size_t)4*NN*16);                \
        cpa16(vb + v_dst, v_src);                                             \
        cpa16(vb + v_dst + 1296u*4u, v_src + 64);                             \
        if (tid < 32) cpa16(sb + (unsigned)ADJ_OFF(BUF)*4u + adj_dst, adj_src);\
        else if (tid < 64) cpa16(sb + (unsigned)A2_OFF(BUF)*4u + a2_dst, a2_src);\
        e_src += TJ*16; v_src += TJ*128; adj_src += TJ; a2_src += TJ*8;       \
    }

    ISSUE_TILE(0)
    cp_commit();

    for (int jt = 0; jt < NN/TJ; ++jt) {
        const int buf = jt & 1;
        cp_wait0();
        __syncthreads();                 // tile jt staged; B(jt-1) done

        if (jt + 1 < NN/TJ) {
            ISSUE_TILE(buf ^ 1)
        }
        cp_commit();

        // ---- phase A: 2 head-pair tasks on row i = w ----
        {
            const float* ebf = &smf[EDGE_OFF(buf) + w*324];
            const float* a2s = &smf[A2_OFF(buf)];
            const int*   ads = (const int*)&smf[ADJ_OFF(buf) + w*20];
            float* tw = &smf[T_OFF + (2*hp)*164 + w*20];
            #pragma unroll
            for (int tt = 0; tt < 2; ++tt) {
                const int j = jl + 8*tt;
                const float* ep = &ebf[j*20];
                ulonglong2 ea = *(const ulonglong2*)(ep);
                ulonglong2 e1 = *(const ulonglong2*)(ep + 4);
                ulonglong2 e2 = *(const ulonglong2*)(ep + 8);
                ulonglong2 e3 = *(const ulonglong2*)(ep + 12);
                ull a2p = *(const ull*)&a2s[j*8 + 2*hp];
                int adv = ads[j];

                ull aA = ffma2(ea.x, wh0[0], 0ull);
                ull aB = ffma2(ea.x, wh1[0], 0ull);
                aA = ffma2(ea.y, wh0[1], aA);  aB = ffma2(ea.y, wh1[1], aB);
                aA = ffma2(e1.x, wh0[2], aA);  aB = ffma2(e1.x, wh1[2], aB);
                aA = ffma2(e1.y, wh0[3], aA);  aB = ffma2(e1.y, wh1[3], aB);
                aA = ffma2(e2.x, wh0[4], aA);  aB = ffma2(e2.x, wh1[4], aB);
                aA = ffma2(e2.y, wh0[5], aA);  aB = ffma2(e2.y, wh1[5], aB);
                aA = ffma2(e3.x, wh0[6], aA);  aB = ffma2(e3.x, wh1[6], aB);
                aA = ffma2(e3.y, wh0[7], aA);  aB = ffma2(e3.y, wh1[7], aB);
                float2 fA = unpack2(aA), fB = unpack2(aB);

                ull x2 = pack2(fA.x + fA.y, fB.x + fB.y);
                x2 = fadd2(x2, baseA);
                x2 = fadd2(x2, a2p);              // x' = CAF*logit
                ull ax = x2 & 0x7fffffff7fffffffULL;
                ull l2 = ffma2(ax, CBO2, x2);     // leaky in log2 domain
                l2 = adv ? l2 : NEG60;
                float2 lf = unpack2(l2);
                tw[j]       = lf.x;
                tw[164 + j] = lf.y;
            }
        }

        __syncthreads();                 // t published

        // ---- phase B: thread (h=w, i=iB, jq): 4 j's packed in pairs ----
        {
            const float* tp = &smf[T_OFF + w*164 + iB*20];
            const float* vp = &smf[VALS_OFF(buf) + w*324];
            #pragma unroll
            for (int pr = 0; pr < 2; ++pr) {
                const int j0 = jq + 8*pr;
                const int j1 = j0 + 4;
                ull x2 = pack2(tp[j0], tp[j1]);
                ull r2 = fadd2(x2, MAGIC2);
                ull rm = fsub2(r2, MAGIC2);
                ull f2 = fsub2(x2, rm);
                unsigned rl = (unsigned)r2, rh = (unsigned)(r2 >> 32);
                float sl = __int_as_float((int)((rl - 0x4B3FFF81u) << 23));
                float sh = __int_as_float((int)((rh - 0x4B3FFF81u) << 23));
                ull p2 = ffma2(P4, f2, P3);
                p2 = ffma2(p2, f2, P2);
                p2 = ffma2(p2, f2, P1);
                p2 = ffma2(p2, f2, ONE2);
                p2 = fmul2(p2, pack2(sl, sh));
                s2 = fadd2(s2, p2);
                float2 pf = unpack2(p2);
                ull pp0 = pack2(pf.x, pf.x);
                ull pp1 = pack2(pf.y, pf.y);
                ulonglong2 va = *(const ulonglong2*)&vp[j0*20];
                ulonglong2 vb = *(const ulonglong2*)&vp[j0*20 + 4];
                ulonglong2 vc = *(const ulonglong2*)&vp[j0*20 + 8];
                ulonglong2 vd = *(const ulonglong2*)&vp[j0*20 + 12];
                acc[0]=ffma2(pp0,va.x,acc[0]); acc[1]=ffma2(pp0,va.y,acc[1]);
                acc[2]=ffma2(pp0,vb.x,acc[2]); acc[3]=ffma2(pp0,vb.y,acc[3]);
                acc[4]=ffma2(pp0,vc.x,acc[4]); acc[5]=ffma2(pp0,vc.y,acc[5]);
                acc[6]=ffma2(pp0,vd.x,acc[6]); acc[7]=ffma2(pp0,vd.y,acc[7]);
                va = *(const ulonglong2*)&vp[j1*20];
                vb = *(const ulonglong2*)&vp[j1*20 + 4];
                vc = *(const ulonglong2*)&vp[j1*20 + 8];
                vd = *(const ulonglong2*)&vp[j1*20 + 12];
                acc[0]=ffma2(pp1,va.x,acc[0]); acc[1]=ffma2(pp1,va.y,acc[1]);
                acc[2]=ffma2(pp1,vb.x,acc[2]); acc[3]=ffma2(pp1,vb.y,acc[3]);
                acc[4]=ffma2(pp1,vc.x,acc[4]); acc[5]=ffma2(pp1,vc.y,acc[5]);
                acc[6]=ffma2(pp1,vd.x,acc[6]); acc[7]=ffma2(pp1,vd.y,acc[7]);
            }
        }
    }

    // reduce across jq (lane bits 0-1)
    #pragma unroll
    for (int m = 1; m <= 2; m <<= 1) {
        #pragma unroll
        for (int q = 0; q < 8; ++q)
            acc[q] = fadd2(acc[q], shflx2(acc[q], m));
        s2 = fadd2(s2, shflx2(s2, m));
    }
    if (jq == 0) {
        float2 sf = unpack2(s2);
        float inv = 1.0f / (sf.x + sf.y);
        int ob = (bi + iB)*128 + w*16;
        #pragma unroll
        for (int q4 = 0; q4 < 4; ++q4) {
            float4 sk = *(const float4*)&g_SKIP[ob + q4*4];
            float2 u0 = unpack2(acc[q4*2]), u1 = unpack2(acc[q4*2 + 1]);
            float4 o;
            o.x = fmaxf(fmaf(u0.x, inv, sk.x), 0.0f);
            o.y = fmaxf(fmaf(u0.y, inv, sk.y), 0.0f);
            o.z = fmaxf(fmaf(u1.x, inv, sk.z), 0.0f);
            o.w = fmaxf(fmaf(u1.y, inv, sk.w), 0.0f);
            *(float4*)&out[ob + q4*4] = o;
        }
    }
    #undef ISSUE_TILE
}

// =====================================================================
extern "C" void kernel_launch(void* const* d_in, const int* in_sizes, int n_in,
                              void* d_out, int out_size)
{
    const float* node   = (const float*)d_in[0];
    const float* edge   = (const float*)d_in[1];
    const float* graph  = (const float*)d_in[2];
    const int*   adj    = (const int*)  d_in[3];
    const float* hidden = (const float*)d_in[4];
    const float* m_w    = (const float*)d_in[5];
    const float* m_b    = (const float*)d_in[6];
    const float* skip_w = (const float*)d_in[7];
    const float* skip_b = (const float*)d_in[8];
    const float* a1_w   = (const float*)d_in[9];
    const float* a1_b   = (const float*)d_in[10];
    const float* a2_w   = (const float*)d_in[11];
    const float* a2_b   = (const float*)d_in[12];
    const float* ae_w   = (const float*)d_in[13];
    const float* ae_b   = (const float*)d_in[14];
    const float* ag_w   = (const float*)d_in[15];
    const float* ag_b   = (const float*)d_in[16];
    float* out = (float*)d_out;

    const int prep_smem = PREP_WORDS * 4;         // 49408 B
    cudaFuncSetAttribute(gat_prep, cudaFuncAttributeMaxDynamicSharedMemorySize,
                         prep_smem);
    const int attn_smem = SMEM_WORDS * 4;         // 49024 B
    cudaFuncSetAttribute(gat_attn, cudaFuncAttributeMaxDynamicSharedMemorySize,
                         attn_smem);

    gat_prep<<<BN/16, 256, prep_smem>>>(node, hidden, m_w, m_b, skip_w, skip_b,
                                        a1_w, a1_b, a2_w, a2_b,
                                        graph, ag_w, ag_b);
    gat_attn<<<4 * (NN/TI), 256, attn_smem>>>(edge, adj, ae_w, ae_b, out);
}

// round 15
// speedup vs baseline: 1.4123x; 1.4123x over previous
#include <cuda_runtime.h>

#define NN 1024
#define BN 4096
#define NH 8
#define TI 16
#define TJ 16

typedef unsigned long long ull;

// ---- scratch ----
__device__ float g_V[BN*128];
__device__ float g_SKIP[BN*128];
__device__ float g_A1[BN*NH];
__device__ float g_A2[BN*NH];
__device__ float g_ATTG[4*NH];

// ---- packed f32x2 helpers ----
__device__ __forceinline__ ull ffma2(ull a, ull b, ull c) {
    ull d; asm("fma.rn.f32x2 %0,%1,%2,%3;" : "=l"(d) : "l"(a), "l"(b), "l"(c)); return d;
}
__device__ __forceinline__ ull fadd2(ull a, ull b) {
    ull d; asm("add.rn.f32x2 %0,%1,%2;" : "=l"(d) : "l"(a), "l"(b)); return d;
}
__device__ __forceinline__ ull fsub2(ull a, ull b) {
    ull d; asm("sub.rn.f32x2 %0,%1,%2;" : "=l"(d) : "l"(a), "l"(b)); return d;
}
__device__ __forceinline__ ull fmul2(ull a, ull b) {
    ull d; asm("mul.rn.f32x2 %0,%1,%2;" : "=l"(d) : "l"(a), "l"(b)); return d;
}
__device__ __forceinline__ ull pack2(float x, float y) {
    ull r; asm("mov.b64 %0,{%1,%2};" : "=l"(r) : "f"(x), "f"(y)); return r;
}
__device__ __forceinline__ float2 unpack2(ull v) {
    float2 r; asm("mov.b64 {%0,%1},%2;" : "=f"(r.x), "=f"(r.y) : "l"(v)); return r;
}
__device__ __forceinline__ ull shflx2(ull v, int m) {
    unsigned lo = (unsigned)v, hi = (unsigned)(v >> 32);
    lo = __shfl_xor_sync(0xffffffffu, lo, m);
    hi = __shfl_xor_sync(0xffffffffu, hi, m);
    return ((ull)hi << 32) | (ull)lo;
}

// ---- cp.async ----
__device__ __forceinline__ void cpa16(unsigned dst, const void* src) {
    asm volatile("cp.async.cg.shared.global [%0], [%1], 16;" :: "r"(dst), "l"(src));
}
__device__ __forceinline__ void cp_commit() {
    asm volatile("cp.async.commit_group;" ::: "memory");
}
__device__ __forceinline__ void cp_wait0() {
    asm volatile("cp.async.wait_group 0;" ::: "memory");
}

// ---- attn smem layout (float words), identical to R10 ----
#define EDGE_OFF(buf) ((buf) ? 5184 : 0)
#define VALS_OFF(buf) ((buf) ? 12960 : 10368)
#define T_OFF         15552
#define ADJ_OFF(buf)  ((buf) ? 18208 : 17888)
#define A2_OFF(buf)   ((buf) ? 18656 : 18528)
#define SMEM_WORDS    18784                    // 75136 bytes

// =====================================================================
// Kernel A: per-node GEMMs. Thread = 4 rows x 4 cols of ONE matrix.
// z transposed in smem (zt[k*20+r]) -> 1 broadcast LDS.128 per k.
// Weights cp.async double-buffered (16 stages x 16 k).
// =====================================================================
#define ZT 20
#define ZT_WORDS (256*ZT)           // 5120
#define PW_OFF ZT_WORDS             // weight buffers base
#define PREP_WORDS (ZT_WORDS + 8192) // 13312 words = 53248 B
#define NSTAGE 16
__global__ __launch_bounds__(256, 3) void gat_prep(
    const float* __restrict__ node, const float* __restrict__ hidden,
    const float* __restrict__ m_w,  const float* __restrict__ m_b,
    const float* __restrict__ skip_w, const float* __restrict__ skip_b,
    const float* __restrict__ a1_w, const float* __restrict__ a1_b,
    const float* __restrict__ a2_w, const float* __restrict__ a2_b,
    const float* __restrict__ graph, const float* __restrict__ ag_w,
    const float* __restrict__ ag_b)
{
    extern __shared__ float sm[];
    float* zt = sm;                          // [k*ZT + r]
    const unsigned sb = (unsigned)__cvta_generic_to_shared(sm);

    const int tid = threadIdx.x;
    const int r0  = blockIdx.x * 16;

    // stage z transposed: thread t -> row r = t&15, col-quad q = t>>4
    for (int t = tid; t < 16*64; t += 256) {
        int r = t & 15, q = t >> 4;
        float4 v = (q < 32) ? ((const float4*)node)[(r0 + r)*32 + q]
                            : ((const float4*)hidden)[(r0 + r)*32 + (q - 32)];
        zt[(4*q + 0)*ZT + r] = v.x;
        zt[(4*q + 1)*ZT + r] = v.y;
        zt[(4*q + 2)*ZT + r] = v.z;
        zt[(4*q + 3)*ZT + r] = v.w;
    }

    // weight cp.async mapping: 1024 chunks/stage, 4/thread
    const float* wsrc[4];
    unsigned     wdst[4];
    #pragma unroll
    for (int k4 = 0; k4 < 4; ++k4) {
        int c = tid + 256*k4;
        int m = c >> 9, cc = c & 511;
        int kl = cc >> 5, q4 = cc & 31;
        wsrc[k4] = (m ? skip_w : m_w) + kl*128 + q4*4;
        wdst[k4] = (unsigned)(m*2048 + kl*128 + q4*4)*4u;
    }

    {
        unsigned base = sb + (unsigned)PW_OFF*4u;
        #pragma unroll
        for (int k4 = 0; k4 < 4; ++k4) cpa16(base + wdst[k4], wsrc[k4]);
        #pragma unroll
        for (int k4 = 0; k4 < 4; ++k4) wsrc[k4] += 16*128;
    }
    cp_commit();

    // thread = (rg 0-3, cg 0-63): matrix m = cg>>5, cols (cg&31)*4, rows rg*4..+3
    const int rg = tid >> 6;
    const int cg = tid & 63;
    const int m  = cg >> 5;
    const int c4 = (cg & 31) * 4;

    ull a[4][2];
    {
        const float* bp = m ? skip_b : m_b;
        ulonglong2 bb = *(const ulonglong2*)&bp[c4];
        #pragma unroll
        for (int r = 0; r < 4; ++r) { a[r][0] = bb.x; a[r][1] = bb.y; }
    }

    const int woff = m*2048 + c4;

    for (int s = 0; s < NSTAGE; ++s) {
        const int buf = s & 1;
        cp_wait0();
        __syncthreads();              // stage s weights visible

        if (s + 1 < NSTAGE) {
            unsigned base = sb + (unsigned)(PW_OFF + (buf ^ 1)*4096)*4u;
            #pragma unroll
            for (int k4 = 0; k4 < 4; ++k4) cpa16(base + wdst[k4], wsrc[k4]);
            #pragma unroll
            for (int k4 = 0; k4 < 4; ++k4) wsrc[k4] += 16*128;
        }
        cp_commit();

        const float* wb = &sm[PW_OFF + buf*4096 + woff];
        const float* zb = &zt[(s*16)*ZT + rg*4];
        #pragma unroll
        for (int kl = 0; kl < 16; ++kl) {
            ulonglong2 W = *(const ulonglong2*)(wb + kl*128);
            float4 z4 = *(const float4*)(zb + kl*ZT);
            ull z0 = pack2(z4.x, z4.x);
            ull z1 = pack2(z4.y, z4.y);
            ull z2 = pack2(z4.z, z4.z);
            ull z3 = pack2(z4.w, z4.w);
            a[0][0] = ffma2(z0, W.x, a[0][0]);  a[0][1] = ffma2(z0, W.y, a[0][1]);
            a[1][0] = ffma2(z1, W.x, a[1][0]);  a[1][1] = ffma2(z1, W.y, a[1][1]);
            a[2][0] = ffma2(z2, W.x, a[2][0]);  a[2][1] = ffma2(z2, W.y, a[2][1]);
            a[3][0] = ffma2(z3, W.x, a[3][0]);  a[3][1] = ffma2(z3, W.y, a[3][1]);
        }
    }
    {
        float* dst = m ? g_SKIP : g_V;
        #pragma unroll
        for (int r = 0; r < 4; ++r) {
            ulonglong2 o; o.x = a[r][0]; o.y = a[r][1];
            *(ulonglong2*)&dst[(size_t)(r0 + rg*4 + r)*128 + c4] = o;
        }
    }

    // ---- att1 / att2 tail + attg ----
    float* ws = sm + PW_OFF;
    __syncthreads();
    for (int t = tid; t < 2048; t += 256) {
        ws[t] = a1_w[t];
        ws[2048 + t] = a2_w[t];
    }
    __syncthreads();
    if (tid < 128) {
        int row = tid >> 3, h = tid & 7;
        float a1a = a1_b[h], a1c = 0.0f, a2a = a2_b[h], a2c = 0.0f;
        #pragma unroll 8
        for (int k = 0; k < 128; ++k) {
            float za = zt[k*ZT + row];
            float zb2 = zt[(k + 128)*ZT + row];
            a1a = fmaf(za, ws[k*8 + h], a1a);
            a1c = fmaf(zb2, ws[(k + 128)*8 + h], a1c);
            a2a = fmaf(za, ws[2048 + k*8 + h], a2a);
            a2c = fmaf(zb2, ws[2048 + (k + 128)*8 + h], a2c);
        }
        g_A1[(r0 + row)*8 + h] = a1a + a1c;
        g_A2[(r0 + row)*8 + h] = a2a + a2c;
    } else if (blockIdx.x == 0 && tid < 160) {
        int t = tid - 128;
        int b = t >> 3, h = t & 7;
        float acc = ag_b[h];
        #pragma unroll 8
        for (int k = 0; k < 128; ++k)
            acc = fmaf(graph[b*128 + k], ag_w[k*8 + h], acc);
        g_ATTG[t] = acc;
    }
}

// =====================================================================
// Kernel C: fused attention — EXACT R10 version (proven 124.6us).
// =====================================================================
__global__ __launch_bounds__(256, 2) void gat_attn(
    const float* __restrict__ edge, const int* __restrict__ adj,
    const float* __restrict__ ae_w, const float* __restrict__ ae_b,
    float* __restrict__ out)
{
    extern __shared__ float smf[];
    const unsigned sb = (unsigned)__cvta_generic_to_shared(smf);

    const int tid = threadIdx.x;
    const int b   = blockIdx.x >> 6;
    const int it  = blockIdx.x & 63;
    const int i0  = it * TI;
    const int bi  = b*NN + i0;

    const int w  = tid >> 5;
    const int hp = tid & 3;
    const int jl = (tid >> 2) & 7;
    const int h  = w;
    const int rB = tid & 31;
    const int ip = rB >> 2;
    const int jq = rB & 3;

    ull wh0[8], wh1[8];
    #pragma unroll
    for (int q = 0; q < 8; ++q) {
        wh0[q] = pack2(ae_w[(2*q)*8 + 2*hp],     ae_w[(2*q+1)*8 + 2*hp]);
        wh1[q] = pack2(ae_w[(2*q)*8 + 2*hp + 1], ae_w[(2*q+1)*8 + 2*hp + 1]);
    }
    ull baseA[2];
    {
        float g0 = g_ATTG[b*8 + 2*hp]     + ae_b[2*hp];
        float g1 = g_ATTG[b*8 + 2*hp + 1] + ae_b[2*hp + 1];
        #pragma unroll
        for (int ih = 0; ih < 2; ++ih) {
            const float* a1p = &g_A1[(size_t)(bi + w + 8*ih)*8 + 2*hp];
            baseA[ih] = pack2(a1p[0] + g0, a1p[1] + g1);
        }
    }

    const float CAf = 0.505f * 1.4426950408889634f;
    const float CBf = 0.495f * 1.4426950408889634f;
    const ull CA2    = pack2(CAf, CAf);
    const ull CB2    = pack2(CBf, CBf);
    const ull NEG60  = pack2(-60.0f, -60.0f);
    const ull MAGIC2 = pack2(12582912.0f, 12582912.0f);
    const ull P4     = pack2(0.0096181291f, 0.0096181291f);
    const ull P3     = pack2(0.0555041087f, 0.0555041087f);
    const ull P2     = pack2(0.2402265070f, 0.2402265070f);
    const ull P1     = pack2(0.6931471806f, 0.6931471806f);
    const ull ONE2   = pack2(1.0f, 1.0f);

    ull acc0[8], acc1[8];
    #pragma unroll
    for (int q = 0; q < 8; ++q) { acc0[q] = 0ull; acc1[q] = 0ull; }
    ull s2 = 0ull;

    const float* e_src[4];
    unsigned     e_dst[4];
    #pragma unroll
    for (int k = 0; k < 4; ++k) {
        int id = tid + 256*k;
        int i = id >> 6, rr = id & 63;
        int j = rr >> 2, c = rr & 3;
        e_src[k] = edge + ((size_t)(bi + i)*NN + j)*16 + c*4;
        e_dst[k] = (unsigned)(i*324 + j*20 + c*4)*4u;
    }
    const float* v_src[2];
    unsigned     v_dst[2];
    #pragma unroll
    for (int k = 0; k < 2; ++k) {
        int id = tid + 256*k;
        int hh = id >> 6, rr = id & 63;
        int j = rr >> 2, d4 = rr & 3;
        v_src[k] = g_V + (size_t)(b*NN + j)*128 + hh*16 + d4*4;
        v_dst[k] = (unsigned)(hh*324 + j*20 + d4*4)*4u;
    }
    const int*   adj_src = adj + (size_t)(bi + (tid >> 2))*NN + (tid & 3)*4;
    const unsigned adj_dst = (unsigned)((tid >> 2)*20 + (tid & 3)*4)*4u;
    const float* a2_src = g_A2 + (size_t)(b*NN + (tid >> 1))*8 + (tid & 1)*4;
    const unsigned a2_dst = (unsigned)((tid >> 1)*8 + (tid & 1)*4)*4u;

    {
        unsigned eb = sb + (unsigned)EDGE_OFF(0)*4u;
        unsigned vb = sb + (unsigned)VALS_OFF(0)*4u;
        #pragma unroll
        for (int k = 0; k < 4; ++k) cpa16(eb + e_dst[k], e_src[k]);
        #pragma unroll
        for (int k = 0; k < 2; ++k) cpa16(vb + v_dst[k], v_src[k]);
        if (tid < 64) cpa16(sb + (unsigned)ADJ_OFF(0)*4u + adj_dst, adj_src);
        if (tid < 32) cpa16(sb + (unsigned)A2_OFF(0)*4u + a2_dst, a2_src);
        #pragma unroll
        for (int k = 0; k < 4; ++k) e_src[k] += TJ*16;
        #pragma unroll
        for (int k = 0; k < 2; ++k) v_src[k] += TJ*128;
        adj_src += TJ;
        a2_src  += TJ*8;
    }
    cp_commit();

    for (int jt = 0; jt < NN/TJ; ++jt) {
        const int buf = jt & 1;
        cp_wait0();
        __syncthreads();

        if (jt + 1 < NN/TJ) {
            unsigned eb = sb + (unsigned)EDGE_OFF(buf ^ 1)*4u;
            unsigned vb = sb + (unsigned)VALS_OFF(buf ^ 1)*4u;
            #pragma unroll
            for (int k = 0; k < 4; ++k) cpa16(eb + e_dst[k], e_src[k]);
            #pragma unroll
            for (int k = 0; k < 2; ++k) cpa16(vb + v_dst[k], v_src[k]);
            if (tid < 64) cpa16(sb + (unsigned)ADJ_OFF(buf ^ 1)*4u + adj_dst, adj_src);
            if (tid < 32) cpa16(sb + (unsigned)A2_OFF(buf ^ 1)*4u + a2_dst, a2_src);
            #pragma unroll
            for (int k = 0; k < 4; ++k) e_src[k] += TJ*16;
            #pragma unroll
            for (int k = 0; k < 2; ++k) v_src[k] += TJ*128;
            adj_src += TJ;
            a2_src  += TJ*8;
        }
        cp_commit();

        const float* ebf = &smf[EDGE_OFF(buf)];
        const float* a2s = &smf[A2_OFF(buf)];
        const int*   ads = (const int*)&smf[ADJ_OFF(buf)];
        #pragma unroll
        for (int tt = 0; tt < 4; ++tt) {
            const int ih = tt >> 1, jh = tt & 1;
            const int i = w + 8*ih;
            const int j = jl + 8*jh;
            const float* ep = &ebf[i*324 + j*20];
            ulonglong2 ea = *(const ulonglong2*)(ep);
            ulonglong2 e1 = *(const ulonglong2*)(ep + 4);
            ulonglong2 e2 = *(const ulonglong2*)(ep + 8);
            ulonglong2 e3 = *(const ulonglong2*)(ep + 12);
            ull a2p = *(const ull*)&a2s[j*8 + 2*hp];
            int adv = ads[i*20 + j];

            ull aA = ffma2(ea.x, wh0[0], 0ull);
            ull aB = ffma2(ea.x, wh1[0], 0ull);
            aA = ffma2(ea.y, wh0[1], aA);  aB = ffma2(ea.y, wh1[1], aB);
            aA = ffma2(e1.x, wh0[2], aA);  aB = ffma2(e1.x, wh1[2], aB);
            aA = ffma2(e1.y, wh0[3], aA);  aB = ffma2(e1.y, wh1[3], aB);
            aA = ffma2(e2.x, wh0[4], aA);  aB = ffma2(e2.x, wh1[4], aB);
            aA = ffma2(e2.y, wh0[5], aA);  aB = ffma2(e2.y, wh1[5], aB);
            aA = ffma2(e3.x, wh0[6], aA);  aB = ffma2(e3.x, wh1[6], aB);
            aA = ffma2(e3.y, wh0[7], aA);  aB = ffma2(e3.y, wh1[7], aB);
            float2 fA = unpack2(aA), fB = unpack2(aB);

            ull t2 = pack2(fA.x + fA.y, fB.x + fB.y);
            t2 = fadd2(t2, baseA[ih]);
            t2 = fadd2(t2, a2p);
            ull ax = t2 & 0x7fffffff7fffffffULL;
            ull l2 = fmul2(t2, CA2);
            l2 = ffma2(ax, CB2, l2);
            l2 = adv ? l2 : NEG60;
            float2 lf = unpack2(l2);
            const int tb = (i >> 1)*36 + (i & 1)*17 + j;
            smf[T_OFF + (2*hp)*292 + tb]     = lf.x;
            smf[T_OFF + (2*hp + 1)*292 + tb] = lf.y;
        }

        __syncthreads();

        const float* tp = &smf[T_OFF + h*292 + ip*36];
        const float* vp = &smf[VALS_OFF(buf) + h*324];
        #pragma unroll
        for (int jj = 0; jj < 4; ++jj) {
            const int j = jj*4 + jq;
            ull x2 = pack2(tp[j], tp[17 + j]);
            ull r2 = fadd2(x2, MAGIC2);
            ull rm = fsub2(r2, MAGIC2);
            ull f2 = fsub2(x2, rm);
            unsigned rl = (unsigned)r2, rh = (unsigned)(r2 >> 32);
            float sl = __int_as_float((int)((rl - 0x4B3FFF81u) << 23));
            float sh = __int_as_float((int)((rh - 0x4B3FFF81u) << 23));
            ull p2 = ffma2(P4, f2, P3);
            p2 = ffma2(p2, f2, P2);
            p2 = ffma2(p2, f2, P1);
            p2 = ffma2(p2, f2, ONE2);
            p2 = fmul2(p2, pack2(sl, sh));
            s2 = fadd2(s2, p2);
            float2 pf = unpack2(p2);
            ull pp0 = pack2(pf.x, pf.x);
            ull pp1 = pack2(pf.y, pf.y);
            ulonglong2 va = *(const ulonglong2*)&vp[j*20];
            ulonglong2 vb = *(const ulonglong2*)&vp[j*20 + 4];
            ulonglong2 vc = *(const ulonglong2*)&vp[j*20 + 8];
            ulonglong2 vd = *(const ulonglong2*)&vp[j*20 + 12];
            acc0[0]=ffma2(pp0,va.x,acc0[0]); acc0[1]=ffma2(pp0,va.y,acc0[1]);
            acc0[2]=ffma2(pp0,vb.x,acc0[2]); acc0[3]=ffma2(pp0,vb.y,acc0[3]);
            acc0[4]=ffma2(pp0,vc.x,acc0[4]); acc0[5]=ffma2(pp0,vc.y,acc0[5]);
            acc0[6]=ffma2(pp0,vd.x,acc0[6]); acc0[7]=ffma2(pp0,vd.y,acc0[7]);
            acc1[0]=ffma2(pp1,va.x,acc1[0]); acc1[1]=ffma2(pp1,va.y,acc1[1]);
            acc1[2]=ffma2(pp1,vb.x,acc1[2]); acc1[3]=ffma2(pp1,vb.y,acc1[3]);
            acc1[4]=ffma2(pp1,vc.x,acc1[4]); acc1[5]=ffma2(pp1,vc.y,acc1[5]);
            acc1[6]=ffma2(pp1,vd.x,acc1[6]); acc1[7]=ffma2(pp1,vd.y,acc1[7]);
        }
    }

    #pragma unroll
    for (int m = 1; m <= 2; m <<= 1) {
        #pragma unroll
        for (int q = 0; q < 8; ++q) {
            acc0[q] = fadd2(acc0[q], shflx2(acc0[q], m));
            acc1[q] = fadd2(acc1[q], shflx2(acc1[q], m));
        }
        s2 = fadd2(s2, shflx2(s2, m));
    }
    if (jq == 0) {
        float2 sf = unpack2(s2);
        float inv0 = 1.0f / sf.x;
        float inv1 = 1.0f / sf.y;
        int r0o = (bi + 2*ip)*128 + h*16;
        #pragma unroll
        for (int q4 = 0; q4 < 4; ++q4) {
            float4 sk = *(const float4*)&g_SKIP[r0o + q4*4];
            float2 u0 = unpack2(acc0[q4*2]), u1 = unpack2(acc0[q4*2 + 1]);
            float4 o;
            o.x = fmaxf(fmaf(u0.x, inv0, sk.x), 0.0f);
            o.y = fmaxf(fmaf(u0.y, inv0, sk.y), 0.0f);
            o.z = fmaxf(fmaf(u1.x, inv0, sk.z), 0.0f);
            o.w = fmaxf(fmaf(u1.y, inv0, sk.w), 0.0f);
            *(float4*)&out[r0o + q4*4] = o;
        }
        int r1o = r0o + 128;
        #pragma unroll
        for (int q4 = 0; q4 < 4; ++q4) {
            float4 sk = *(const float4*)&g_SKIP[r1o + q4*4];
            float2 u0 = unpack2(acc1[q4*2]), u1 = unpack2(acc1[q4*2 + 1]);
            float4 o;
            o.x = fmaxf(fmaf(u0.x, inv1, sk.x), 0.0f);
            o.y = fmaxf(fmaf(u0.y, inv1, sk.y), 0.0f);
            o.z = fmaxf(fmaf(u1.x, inv1, sk.z), 0.0f);
            o.w = fmaxf(fmaf(u1.y, inv1, sk.w), 0.0f);
            *(float4*)&out[r1o + q4*4] = o;
        }
    }
}

// =====================================================================
extern "C" void kernel_launch(void* const* d_in, const int* in_sizes, int n_in,
                              void* d_out, int out_size)
{
    const float* node   = (const float*)d_in[0];
    const float* edge   = (const float*)d_in[1];
    const float* graph  = (const float*)d_in[2];
    const int*   adj    = (const int*)  d_in[3];
    const float* hidden = (const float*)d_in[4];
    const float* m_w    = (const float*)d_in[5];
    const float* m_b    = (const float*)d_in[6];
    const float* skip_w = (const float*)d_in[7];
    const float* skip_b = (const float*)d_in[8];
    const float* a1_w   = (const float*)d_in[9];
    const float* a1_b   = (const float*)d_in[10];
    const float* a2_w   = (const float*)d_in[11];
    const float* a2_b   = (const float*)d_in[12];
    const float* ae_w   = (const float*)d_in[13];
    const float* ae_b   = (const float*)d_in[14];
    const float* ag_w   = (const float*)d_in[15];
    const float* ag_b   = (const float*)d_in[16];
    float* out = (float*)d_out;

    const int prep_smem = PREP_WORDS * 4;         // 53248 B
    cudaFuncSetAttribute(gat_prep, cudaFuncAttributeMaxDynamicSharedMemorySize,
                         prep_smem);
    const int attn_smem = SMEM_WORDS * 4;         // 75136 B
    cudaFuncSetAttribute(gat_attn, cudaFuncAttributeMaxDynamicSharedMemorySize,
                         attn_smem);

    gat_prep<<<BN/16, 256, prep_smem>>>(node, hidden, m_w, m_b, skip_w, skip_b,
                                        a1_w, a1_b, a2_w, a2_b,
                                        graph, ag_w, ag_b);
    gat_attn<<<4 * (NN/TI), 256, attn_smem>>>(edge, adj, ae_w, ae_b, out);
}